// round 17
// baseline (speedup 1.0000x reference)
#include <cuda_runtime.h>
#include <cuda_fp16.h>
#include <cstdint>

#define BN 2048   // B*N rows
#define NN 256    // N (neighbors)
#define D  128
#define E  64

__device__ __forceinline__ float tanh_fast(float x) {
    float y;
    asm("tanh.approx.f32 %0, %1;" : "=f"(y) : "f"(x));
    return y;
}

__device__ __forceinline__ uint32_t pack_h2(float a, float b) {
    __half2 v = __floats2half2_rn(a, b);   // a = low half (even k)
    uint32_t r;
    memcpy(&r, &v, 4);
    return r;
}

// ---------------------------------------------------------------------------
// FUSED kernel: 4 (b,i) rows per CTA (grid 512).  Single launch.
// Phase A (gate/agg, per sub-row): W2 staged once (0.5*W2 fp16 packed),
//   hW1 prologue overlapped with staging, 32-row double-buffered j-tiles,
//   fp16 m16n8k16 mma.sync, tanh-space masked sum/max -> s_agg (SMEM only).
// Phase B (update MLP + LN, per CTA tail): transposed inputs from SMEM,
//   U1/U2 staged in 32x128 s_w tiles (overlaying dead sW2T), FFMA2 chains
//   (bitwise-identical to the proven k3), residual + LayerNorm -> out.
// No intermediate global traffic, no second kernel.
// ---------------------------------------------------------------------------
// float-index SMEM map (total 11104 floats = 44416 B):
//  [0..4607]    sW2T (u32 view)   | phase B: s_w 32x128 tile (4096 fl)
//  [4608..6911] sRh 2x(32x36 u32) | phase B: s_inT [384][4] (1536 fl)
//  [6912..7167] s_hW1x [4][64]
//  [7168..7359] sW1e [3][64]
//  [7360..7487] s_b2 (=0.5*b2)
//  [7488..7999] s_hx [4][128]
//  [8000..8255] s_redS [2][128]
//  [8256..8511] s_redT [2][128]
//  [8768..9023] s_jidx (int)
//  [9024..9031] s_misc (int)
//  [9032..9543] s_midT [128][4]
//  [9544..10071] s_x [4][132]
//  [10072..10583] s_aggme [4][128]
//  [10584..11095] s_aggmx [4][128]
#define K2_SMEM_BYTES (11104 * 4)

__global__ void __launch_bounds__(256) k_fused(
    const float* __restrict__ h, const float* __restrict__ ef,
    const unsigned char* __restrict__ adj,
    const float* __restrict__ W1, const float* __restrict__ b1,
    const float* __restrict__ W2, const float* __restrict__ b2,
    const float* __restrict__ U1, const float* __restrict__ b3,
    const float* __restrict__ U2, const float* __restrict__ b4,
    const float* __restrict__ gamma, const float* __restrict__ beta,
    float* __restrict__ out) {
    extern __shared__ float sm[];
    uint32_t* sW2T  = (uint32_t*)sm;
    uint32_t* sRh   = (uint32_t*)(sm + 4608);
    float* s_hW1x = sm + 6912;
    float* sW1e   = sm + 7168;
    float* s_b2   = sm + 7360;
    float* s_hx   = sm + 7488;
    float* s_redS = sm + 8000;
    float* s_redT = sm + 8256;
    int*   s_jidx = (int*)(sm + 8768);
    int*   s_misc = (int*)(sm + 9024);
    float* s_midT = sm + 9032;    // [128][4]
    float* s_x    = sm + 9544;    // [4][132]
    float* s_aggme= sm + 10072;   // [4][128]
    float* s_aggmx= sm + 10584;   // [4][128]

    const int bi0  = blockIdx.x * 4;
    const int tid  = threadIdx.x;
    const int lane = tid & 31;
    const int warp = tid >> 5;
    const int gid  = lane >> 2;   // 0..7
    const int tg   = lane & 3;    // 0..3
    const int wm   = warp & 1;    // row-half (16 rows)
    const int wn   = warp >> 1;   // col group (32 cols)

    if (tid < 128) {
        const int r = tid >> 5, c = tid & 31;
        ((float4*)&s_hx[r * 128])[c] = ((const float4*)(h + (size_t)(bi0 + r) * D))[c];
    }
    for (int idx = tid; idx < 32 * D; idx += 256) {
        const int ep = idx >> 7, d = idx & 127;
        const float w0 = 0.5f * W2[(2 * ep) * D + d];
        const float w1 = 0.5f * W2[(2 * ep + 1) * D + d];
        sW2T[d * 36 + ep] = pack_h2(w0, w1);
    }
    for (int idx = tid; idx < 3 * E; idx += 256) sW1e[idx] = W1[D * E + idx];
    if (tid < D) s_b2[tid] = 0.5f * b2[tid];

    // hW1 prologue (h via __ldg: overlaps staging loads)
    {
        const int r = tid >> 6;
        const int e = tid & 63;
        const float* hr = h + (size_t)(bi0 + r) * D;
        float a0 = 0.f, a1 = 0.f;
#pragma unroll 8
        for (int k = 0; k < 128; k += 2) {
            a0 = fmaf(__ldg(hr + k),     W1[k * E + e],       a0);
            a1 = fmaf(__ldg(hr + k + 1), W1[(k + 1) * E + e], a1);
        }
        s_hW1x[r * 64 + e] = a0 + a1 + b1[e];
    }

    // ================= Phase A: gate + aggregation per sub-row =============
    for (int sub = 0; sub < 4; sub++) {
        const int bi = bi0 + sub;
        __syncthreads();

        const float* s_hW1 = s_hW1x + sub * 64;
        const float* s_h   = s_hx + sub * 128;

        const bool m = adj[(size_t)bi * NN + tid] != 0;
        const unsigned bal = __ballot_sync(0xffffffffu, m);
        if (lane == 0) s_misc[warp] = __popc(bal);
        __syncthreads();
        int base = 0, cnt = 0;
#pragma unroll
        for (int w = 0; w < 8; w++) {
            const int c = s_misc[w];
            if (w < warp) base += c;
            cnt += c;
        }
        if (m) s_jidx[base + __popc(bal & ((1u << lane) - 1u))] = tid;
        __syncthreads();

        float bh[8], sgn[8];
#pragma unroll
        for (int nt = 0; nt < 4; nt++)
#pragma unroll
            for (int q = 0; q < 2; q++) {
                const int d = wn * 32 + nt * 8 + 2 * tg + q;
                bh[nt * 2 + q]  = s_b2[d];
                sgn[nt * 2 + q] = (s_h[d] >= 0.f) ? 1.f : -1.f;
            }

        float S[8], T[8];
#pragma unroll
        for (int i = 0; i < 8; i++) { S[i] = 0.f; T[i] = -1e30f; }

        const int nTiles = (cnt + 31) >> 5;
        const int rrow = tid >> 3;          // 0..31 (build row)
        const int re0  = (tid & 7) << 3;    // e base (8 per thread)
        const int rp0  = (tid & 7) << 2;    // e-pair base

        const float4* hw4 = (const float4*)(s_hW1 + re0);
        const float4* we0 = (const float4*)(sW1e + re0);
        const float4* we1 = (const float4*)(sW1e + 64 + re0);
        const float4* we2 = (const float4*)(sW1e + 128 + re0);

        auto build_tile = [&](int t, uint32_t* buf) {
            float f0 = 0.f, f1 = 0.f, f2v = 0.f;
            const int jg = t * 32 + rrow;
            if (jg < cnt) {
                const float* p = ef + ((size_t)bi * NN + s_jidx[jg]) * 3;
                f0 = p[0]; f1 = p[1]; f2v = p[2];
            }
#pragma unroll
            for (int i4 = 0; i4 < 2; i4++) {
                const float4 hv = hw4[i4];
                const float4 a  = we0[i4];
                const float4 b  = we1[i4];
                const float4 cc = we2[i4];
                const float p0 = fmaxf(hv.x + f0 * a.x + f1 * b.x + f2v * cc.x, 0.f);
                const float p1 = fmaxf(hv.y + f0 * a.y + f1 * b.y + f2v * cc.y, 0.f);
                const float p2 = fmaxf(hv.z + f0 * a.z + f1 * b.z + f2v * cc.z, 0.f);
                const float p3 = fmaxf(hv.w + f0 * a.w + f1 * b.w + f2v * cc.w, 0.f);
                buf[rrow * 36 + rp0 + i4 * 2]     = pack_h2(p0, p1);
                buf[rrow * 36 + rp0 + i4 * 2 + 1] = pack_h2(p2, p3);
            }
        };

        build_tile(0, sRh);

        for (int t = 0; t < nTiles; t++) {
            __syncthreads();
            if (t + 1 < nTiles) build_tile(t + 1, sRh + ((t + 1) & 1) * 1152);

            const uint32_t* bufc = sRh + (t & 1) * 1152;

            float c[4][4];
#pragma unroll
            for (int nt = 0; nt < 4; nt++)
#pragma unroll
                for (int q = 0; q < 4; q++) c[nt][q] = bh[nt * 2 + (q & 1)];

#pragma unroll
            for (int kc = 0; kc < 4; kc++) {
                const int kp = kc * 8;
                uint32_t a[4], b[4][2];
                {
                    const int row = wm * 16 + gid;
                    const uint32_t* pr = bufc + row * 36 + kp + tg;
                    a[0] = pr[0];
                    a[1] = pr[8 * 36];
                    a[2] = pr[4];
                    a[3] = pr[8 * 36 + 4];
                }
#pragma unroll
                for (int nt = 0; nt < 4; nt++) {
                    const int col = wn * 32 + nt * 8 + gid;
                    const uint32_t* pb = sW2T + col * 36 + kp + tg;
                    b[nt][0] = pb[0];
                    b[nt][1] = pb[4];
                }
#pragma unroll
                for (int nt = 0; nt < 4; nt++) {
                    asm("mma.sync.aligned.m16n8k16.row.col.f32.f16.f16.f32 "
                        "{%0,%1,%2,%3}, {%4,%5,%6,%7}, {%8,%9}, {%0,%1,%2,%3};\n"
                        : "+f"(c[nt][0]), "+f"(c[nt][1]),
                          "+f"(c[nt][2]), "+f"(c[nt][3])
                        : "r"(a[0]), "r"(a[1]), "r"(a[2]), "r"(a[3]),
                          "r"(b[nt][0]), "r"(b[nt][1]));
                }
            }

#pragma unroll
            for (int q = 0; q < 4; q++) {
                const int rloc = wm * 16 + gid + ((q >> 1) << 3);
                const float vm = ((t * 32 + rloc) < cnt) ? 1.f : 0.f;
#pragma unroll
                for (int nt = 0; nt < 4; nt++) {
                    const int si = nt * 2 + (q & 1);
                    const float th = tanh_fast(c[nt][q]);
                    S[si] = fmaf(vm, th, S[si]);
                    float tt = sgn[si] * th;
                    tt = (vm != 0.f) ? tt : -1e30f;
                    T[si] = fmaxf(T[si], tt);
                }
            }
        }

#pragma unroll
        for (int i = 0; i < 8; i++) {
#pragma unroll
            for (int off = 4; off < 32; off <<= 1) {
                S[i] += __shfl_xor_sync(0xffffffffu, S[i], off);
                T[i]  = fmaxf(T[i], __shfl_xor_sync(0xffffffffu, T[i], off));
            }
        }
        __syncthreads();
        if (lane < 4) {
#pragma unroll
            for (int nt = 0; nt < 4; nt++)
#pragma unroll
                for (int q = 0; q < 2; q++) {
                    const int d = wn * 32 + nt * 8 + 2 * lane + q;
                    const int si = nt * 2 + q;
                    s_redS[wm * 128 + d] = S[si];
                    s_redT[wm * 128 + d] = T[si];
                }
        }
        __syncthreads();
        if (tid < D) {
            const float St = s_redS[tid] + s_redS[128 + tid];
            const float Tt = fmaxf(s_redT[tid], s_redT[128 + tid]);
            const float hv = s_h[tid];
            const float cntf = (float)cnt;
            const float cl = (cnt > 0) ? cntf : 1.f;
            const float Sg = fmaf(0.5f, St, 0.5f * cntf);
            s_aggme[sub * 128 + tid] = Sg * hv / cl;
            float amax = 0.f;
            if (cnt > 0) {
                const float half_sgn = (hv >= 0.f) ? 0.5f : -0.5f;
                amax = hv * fmaf(half_sgn, Tt, 0.5f);
            }
            s_aggmx[sub * 128 + tid] = amax;
        }
    }

    // ================= Phase B: update MLP + residual + LayerNorm ==========
    __syncthreads();   // all s_agg written; sW2T/sRh regions now free

    float* s_w   = sm;            // 32x128 weight tile (overlays sW2T)
    float* s_inT = sm + 4608;     // [384][4] transposed inputs (overlays sRh)

    // Stage transposed inputs [k][row] from SMEM sources
    for (int idx = tid; idx < 1536; idx += 256) {
        const int k = idx >> 2, r = idx & 3;
        float v;
        if (k < 128)       v = s_hx[r * 128 + k];
        else if (k < 256)  v = s_aggme[r * 128 + (k - 128)];
        else               v = s_aggmx[r * 128 + (k - 256)];
        s_inT[k * 4 + r] = v;
    }

    const int e  = tid & 127;     // output column
    const int rh = tid >> 7;      // 0/1 -> rows 2rh, 2rh+1

    int lk[4], lc[4];
#pragma unroll
    for (int i = 0; i < 4; i++) { const int idx = tid + i * 256; lk[i] = idx >> 5; lc[i] = idx & 31; }

    unsigned long long a01 = 0ull;
    float4 pf[4];
#pragma unroll
    for (int i = 0; i < 4; i++) pf[i] = ((const float4*)(U1 + lk[i] * D))[lc[i]];
    __syncthreads();   // s_inT staged; sW2T reads long done

    for (int kc = 0; kc < 384; kc += 32) {
#pragma unroll
        for (int i = 0; i < 4; i++) *(float4*)&s_w[lk[i] * 128 + lc[i] * 4] = pf[i];
        __syncthreads();
        if (kc + 32 < 384) {
#pragma unroll
            for (int i = 0; i < 4; i++)
                pf[i] = ((const float4*)(U1 + (kc + 32 + lk[i]) * D))[lc[i]];
        }
#pragma unroll
        for (int kk = 0; kk < 32; kk++) {
            const float wv = s_w[kk * 128 + e];
            const unsigned long long v = *(const unsigned long long*)&s_inT[(kc + kk) * 4 + rh * 2];
            unsigned long long wp;
            asm("mov.b64 %0, {%1, %1};" : "=l"(wp) : "r"(__float_as_uint(wv)));
            asm("fma.rn.f32x2 %0, %1, %2, %0;" : "+l"(a01) : "l"(v), "l"(wp));
        }
        __syncthreads();
    }
    {
        const float bb = b3[e];
        uint32_t l0, h0;
        asm("mov.b64 {%0, %1}, %2;" : "=r"(l0), "=r"(h0) : "l"(a01));
        s_midT[e * 4 + rh * 2 + 0] = fmaxf(__uint_as_float(l0) + bb, 0.f);
        s_midT[e * 4 + rh * 2 + 1] = fmaxf(__uint_as_float(h0) + bb, 0.f);
    }
    a01 = 0ull;
#pragma unroll
    for (int i = 0; i < 4; i++) pf[i] = ((const float4*)(U2 + lk[i] * D))[lc[i]];
    __syncthreads();   // s_midT complete + s_w free

    for (int kc = 0; kc < 128; kc += 32) {
#pragma unroll
        for (int i = 0; i < 4; i++) *(float4*)&s_w[lk[i] * 128 + lc[i] * 4] = pf[i];
        __syncthreads();
        if (kc + 32 < 128) {
#pragma unroll
            for (int i = 0; i < 4; i++)
                pf[i] = ((const float4*)(U2 + (kc + 32 + lk[i]) * D))[lc[i]];
        }
#pragma unroll
        for (int kk = 0; kk < 32; kk++) {
            const float wv = s_w[kk * 128 + e];
            const unsigned long long v = *(const unsigned long long*)&s_midT[(kc + kk) * 4 + rh * 2];
            unsigned long long wp;
            asm("mov.b64 %0, {%1, %1};" : "=l"(wp) : "r"(__float_as_uint(wv)));
            asm("fma.rn.f32x2 %0, %1, %2, %0;" : "+l"(a01) : "l"(v), "l"(wp));
        }
        __syncthreads();
    }
    {
        const float b4v = b4[e];
        uint32_t l0, h0;
        asm("mov.b64 {%0, %1}, %2;" : "=r"(l0), "=r"(h0) : "l"(a01));
        const int r0l = rh * 2;
        s_x[(r0l + 0) * 132 + e] = s_hx[(r0l + 0) * 128 + e] + __uint_as_float(l0) + b4v;
        s_x[(r0l + 1) * 132 + e] = s_hx[(r0l + 1) * 128 + e] + __uint_as_float(h0) + b4v;
    }
    __syncthreads();

    // LayerNorm: warps 0-3, one row each
    if (warp < 4) {
        const int r = warp;
        float s = 0.f, s2 = 0.f, v[4];
#pragma unroll
        for (int i = 0; i < 4; i++) {
            v[i] = s_x[r * 132 + lane + i * 32];
            s += v[i]; s2 += v[i] * v[i];
        }
#pragma unroll
        for (int off = 1; off < 32; off <<= 1) {
            s  += __shfl_xor_sync(0xffffffffu, s, off);
            s2 += __shfl_xor_sync(0xffffffffu, s2, off);
        }
        const float mu  = s * (1.f / 128.f);
        const float var = s2 * (1.f / 128.f) - mu * mu;
        const float inv = rsqrtf(var + 1e-5f);
#pragma unroll
        for (int i = 0; i < 4; i++) {
            const int d = lane + i * 32;
            out[(size_t)(bi0 + r) * D + d] = (v[i] - mu) * inv * gamma[d] + beta[d];
        }
    }
}

// ---------------------------------------------------------------------------
extern "C" void kernel_launch(void* const* d_in, const int* in_sizes, int n_in,
                              void* d_out, int out_size) {
    const float* h    = (const float*)d_in[0];
    const float* ef   = (const float*)d_in[1];
    const unsigned char* adj = (const unsigned char*)d_in[2];
    const float* W1   = (const float*)d_in[3];
    const float* b1   = (const float*)d_in[4];
    const float* W2   = (const float*)d_in[5];
    const float* b2   = (const float*)d_in[6];
    const float* U1   = (const float*)d_in[7];
    const float* b3   = (const float*)d_in[8];
    const float* U2   = (const float*)d_in[9];
    const float* b4   = (const float*)d_in[10];
    const float* gamma= (const float*)d_in[11];
    const float* beta = (const float*)d_in[12];
    float* out = (float*)d_out;

    cudaFuncSetAttribute(k_fused, cudaFuncAttributeMaxDynamicSharedMemorySize,
                         K2_SMEM_BYTES);

    k_fused<<<BN / 4, 256, K2_SMEM_BYTES>>>(h, ef, adj, W1, b1, W2, b2,
                                            U1, b3, U2, b4, gamma, beta, out);
}